// round 16
// baseline (speedup 1.0000x reference)
#include <cuda_runtime.h>
#include <cuda_fp16.h>
#include <cstdint>
#include <cstddef>

#define BB 16
#define NN 96
#define DD 256
#define MROWS (BB * NN * NN)          // 147456

// Scratch (allocation-free device globals)
__device__ __half g_W1h[DD * DD];    // transposed [n][k] fp16
__device__ __half g_W2h[DD * DD];    // transposed [n][k] fp16
__device__ __half g_Ah[BB * NN * NN];

// ---------------------------------------------------------------------------
// helpers
// ---------------------------------------------------------------------------
__device__ __forceinline__ uint32_t packh2(float a, float b) {
    __half2 h = __floats2half2_rn(a, b);
    return *reinterpret_cast<uint32_t*>(&h);
}

__device__ __forceinline__ void mma16(float* c, const uint32_t* a, const uint32_t* b) {
    asm volatile("mma.sync.aligned.m16n8k16.row.col.f32.f16.f16.f32 "
        "{%0,%1,%2,%3}, {%4,%5,%6,%7}, {%8,%9}, {%0,%1,%2,%3};"
        : "+f"(c[0]), "+f"(c[1]), "+f"(c[2]), "+f"(c[3])
        : "r"(a[0]), "r"(a[1]), "r"(a[2]), "r"(a[3]), "r"(b[0]), "r"(b[1]));
}

__device__ __forceinline__ void ldsm4(uint32_t* r, uint32_t addr) {
    asm volatile("ldmatrix.sync.aligned.m8n8.x4.shared.b16 {%0,%1,%2,%3}, [%4];"
        : "=r"(r[0]), "=r"(r[1]), "=r"(r[2]), "=r"(r[3]) : "r"(addr));
}

__device__ __forceinline__ void ldsm4t(uint32_t* r, uint32_t addr) {
    asm volatile("ldmatrix.sync.aligned.m8n8.x4.trans.shared.b16 {%0,%1,%2,%3}, [%4];"
        : "=r"(r[0]), "=r"(r[1]), "=r"(r[2]), "=r"(r[3]) : "r"(addr));
}

__device__ __forceinline__ void cpa16(uint32_t dst, const void* src) {
    asm volatile("cp.async.cg.shared.global [%0], [%1], 16;\n" :: "r"(dst), "l"(src));
}
__device__ __forceinline__ void cpa_commit() {
    asm volatile("cp.async.commit_group;\n");
}
template <int N>
__device__ __forceinline__ void cpa_wait() {
    asm volatile("cp.async.wait_group %0;\n" :: "n"(N));
}

// ---------------------------------------------------------------------------
// prepasses
// ---------------------------------------------------------------------------
__global__ void transpose_cvt_kernel(const float* __restrict__ src,
                                     __half* __restrict__ dst) {
    __shared__ float t[32][33];
    int bx = blockIdx.x * 32;
    int by = blockIdx.y * 32;
    int x = threadIdx.x, y0 = threadIdx.y;
#pragma unroll
    for (int r = 0; r < 32; r += 8)
        t[y0 + r][x] = src[(size_t)(by + y0 + r) * DD + bx + x];
    __syncthreads();
#pragma unroll
    for (int r = 0; r < 32; r += 8)
        dst[(size_t)(bx + y0 + r) * DD + by + x] = __float2half_rn(t[x][y0 + r]);
}

__global__ void cvt_half_kernel(const float4* __restrict__ src,
                                uint2* __restrict__ dst, int n4) {
    int i = blockIdx.x * blockDim.x + threadIdx.x;
    if (i < n4) {
        float4 v = src[i];
        uint2 o;
        o.x = packh2(v.x, v.y);
        o.y = packh2(v.z, v.w);
        dst[i] = o;
    }
}

// ---------------------------------------------------------------------------
// MEGA-FUSED, 24-warp, 4-stage B pipeline. Per CTA (j, b): rows (b, i=0..95, j).
//   GEMM1: h1 = relu(X@W1+b1)        (M=96, N=256, K=256)
//   GEMM2: h2 = mask*relu(h1@W2+b2)  (h1 in smem, in place)
//   GEMM3: out[b,i,j,:] = sum_k Aadj[b,i,k]*h2[k,:]   (h2 in smem, K=96)
// 768 threads (24 warps, 6/SMSP), warp grid 3M x 8N, warp tile 32x32.
// smem: A 4x12KB (X->h1->h2 in place) + adj 20KB + B 4x32KB = 196KB.
// W1 t0-3 issued up-front (G0-G3); W2 tile t refills stage t after the
// pre-tile-(t+1) barrier proves all readers are done -> no post-compute syncs.
// ---------------------------------------------------------------------------
__global__ __launch_bounds__(768)
void mega24(const float* __restrict__ X, const __half* __restrict__ W1t,
            const __half* __restrict__ W2t, const float* __restrict__ b1,
            const float* __restrict__ b2, const int* __restrict__ mask,
            const __half* __restrict__ Aall, float* __restrict__ Out)
{
    extern __shared__ __align__(16) char smem[];
    const uint32_t sBase = (uint32_t)__cvta_generic_to_shared(smem);
    const uint32_t adjB  = sBase + 49152;     // 96 x 208B (pad to 20480)
    const uint32_t bBase = sBase + 69632;     // B: 4 stages x 32KB

    const int tid  = threadIdx.x;
    const int lane = tid & 31;
    const int warp = tid >> 5;                // 0..23
    const int grp  = lane >> 2;
    const int c4   = lane & 3;
    const int warpM = (warp >> 3) * 32;       // 0/32/64
    const int warpN = (warp & 7) * 32;        // 0..224
    const int j = blockIdx.x;                 // 0..95
    const int b = blockIdx.y;                 // 0..15

    float acc[2][4][4];
#pragma unroll
    for (int i = 0; i < 2; i++)
#pragma unroll
        for (int jj = 0; jj < 4; jj++)
#pragma unroll
            for (int r = 0; r < 4; r++) acc[i][jj][r] = 0.0f;

    // X tile loader: rows (b, row, j), 96 rows x 8 chunks = 768 -> 1/thread
    auto ldX = [&](int t) {
        int row = tid >> 3, ch = tid & 7;
        size_t gr = ((size_t)(b * NN + row)) * NN + j;
        const float* p = X + gr * DD + t * 64 + ch * 8;
        float4 u = *reinterpret_cast<const float4*>(p);
        float4 v = *reinterpret_cast<const float4*>(p + 4);
        uint4 val;
        val.x = packh2(u.x, u.y);
        val.y = packh2(u.z, u.w);
        val.z = packh2(v.x, v.y);
        val.w = packh2(v.z, v.w);
        *reinterpret_cast<uint4*>(smem + t * 12288 + row * 128 +
                                  ((ch ^ (row & 7)) << 4)) = val;
    };
    // B loader: 256 rows x 8 chunks = 2048 -> 3 reps, last partial
    auto cpaB = [&](const __half* Wt, int t, int stage) {
#pragma unroll
        for (int rep = 0; rep < 3; rep++) {
            int g = tid + rep * 768;
            if (g < 2048) {
                int row = g >> 3, ch = g & 7;
                cpa16(bBase + stage * 32768 + row * 128 + ((ch ^ (row & 7)) << 4),
                      Wt + (size_t)row * DD + t * 64 + ch * 8);
            }
        }
    };
    auto cpaAdj = [&]() {
        const __half* Aab = Aall + (size_t)b * NN * NN;
#pragma unroll
        for (int rep = 0; rep < 2; rep++) {
            int idx = tid + rep * 768;
            if (idx < 96 * 12) {
                int row = idx / 12, ch = idx % 12;
                cpa16(adjB + row * 208 + ch * 16, Aab + row * 96 + ch * 8);
            }
        }
    };

    auto computeTile = [&](uint32_t aSt, uint32_t bSt) {
#pragma unroll
        for (int ks = 0; ks < 4; ks++) {
            uint32_t afr[2][4];
#pragma unroll
            for (int mt = 0; mt < 2; mt++) {
                int m  = warpM + mt * 16 + (lane & 15);
                int ch = 2 * ks + (lane >> 4);
                ldsm4(afr[mt], aSt + m * 128 + ((ch ^ (m & 7)) << 4));
            }
            uint32_t bfr[2][4];
#pragma unroll
            for (int np = 0; np < 2; np++) {
                int n  = warpN + np * 16 + 8 * (lane >> 4) + (lane & 7);
                int ch = 2 * ks + ((lane >> 3) & 1);
                ldsm4(bfr[np], bSt + n * 128 + ((ch ^ (n & 7)) << 4));
            }
#pragma unroll
            for (int mt = 0; mt < 2; mt++)
#pragma unroll
                for (int np = 0; np < 2; np++) {
                    mma16(acc[mt][2 * np + 0], afr[mt], bfr[np] + 0);
                    mma16(acc[mt][2 * np + 1], afr[mt], bfr[np] + 2);
                }
        }
    };

    // ---- prologue: W1 t0-3 (G0-G3, adj rides with G3); X staged ----
    cpaB(W1t, 0, 0); cpa_commit();            // G0
    cpaB(W1t, 1, 1); cpa_commit();            // G1
    cpaB(W1t, 2, 2); cpa_commit();            // G2
    cpaB(W1t, 3, 3); cpaAdj(); cpa_commit();  // G3 (+adj)
    ldX(0); ldX(1); ldX(2); ldX(3);

    // ---- GEMM1: h1 = X @ W1 (stages 0-3); W2 refills after next barrier ----
    cpa_wait<3>(); __syncthreads();           // G0 done
    computeTile(sBase + 0 * 12288, bBase + 0 * 32768);

    cpa_wait<2>(); __syncthreads();           // G1 done; all warps past t0
    cpaB(W2t, 0, 0); cpa_commit();            // G4 -> s0
    computeTile(sBase + 1 * 12288, bBase + 1 * 32768);

    cpa_wait<2>(); __syncthreads();           // G2 done; all past t1
    cpaB(W2t, 1, 1); cpa_commit();            // G5 -> s1
    computeTile(sBase + 2 * 12288, bBase + 2 * 32768);

    cpa_wait<2>(); __syncthreads();           // G3 done (adj in too); all past t2
    cpaB(W2t, 2, 2); cpa_commit();            // G6 -> s2
    computeTile(sBase + 3 * 12288, bBase + 3 * 32768);

    __syncthreads();                          // all X + s3 reads done
    cpaB(W2t, 3, 3); cpa_commit();            // G7 -> s3

    // ---- epilogue1: h1 = relu(acc + b1) -> A region (fp16), zero acc ----
#pragma unroll
    for (int mt = 0; mt < 2; mt++) {
#pragma unroll
        for (int pr = 0; pr < 2; pr++) {
            int rl = warpM + mt * 16 + grp + 8 * pr;   // 0..95
#pragma unroll
            for (int nt = 0; nt < 4; nt++) {
                int col = warpN + nt * 8 + 2 * c4;
                float2 bb = *reinterpret_cast<const float2*>(b1 + col);
                float v0 = fmaxf(acc[mt][nt][2 * pr + 0] + bb.x, 0.0f);
                float v1 = fmaxf(acc[mt][nt][2 * pr + 1] + bb.y, 0.0f);
                int tt = col >> 6;
                int ch = (col & 63) >> 3;
                *reinterpret_cast<uint32_t*>(smem + tt * 12288 + rl * 128 +
                    ((ch ^ (rl & 7)) << 4) + (col & 7) * 2) = packh2(v0, v1);
            }
        }
    }
#pragma unroll
    for (int i = 0; i < 2; i++)
#pragma unroll
        for (int jj = 0; jj < 4; jj++)
#pragma unroll
            for (int r = 0; r < 4; r++) acc[i][jj][r] = 0.0f;

    // ---- GEMM2: h2 = h1 @ W2 (stages 0-3) ----
    cpa_wait<3>(); __syncthreads();           // G4 done + h1 visible
    computeTile(sBase + 0 * 12288, bBase + 0 * 32768);

    cpa_wait<2>(); __syncthreads();           // G5 done
    computeTile(sBase + 1 * 12288, bBase + 1 * 32768);

    cpa_wait<1>(); __syncthreads();           // G6 done
    computeTile(sBase + 2 * 12288, bBase + 2 * 32768);

    cpa_wait<0>(); __syncthreads();           // G7 done
    computeTile(sBase + 3 * 12288, bBase + 3 * 32768);

    __syncthreads();                          // all h1 reads done

    // ---- epilogue2: h2 = mask * relu(acc + b2) -> A region (fp16) ----
#pragma unroll
    for (int mt = 0; mt < 2; mt++) {
#pragma unroll
        for (int pr = 0; pr < 2; pr++) {
            int rl = warpM + mt * 16 + grp + 8 * pr;   // 0..95 (= i)
            float mv = (mask[((size_t)(b * NN + rl)) * NN + j] != 0) ? 1.0f : 0.0f;
#pragma unroll
            for (int nt = 0; nt < 4; nt++) {
                int col = warpN + nt * 8 + 2 * c4;
                float2 bb = *reinterpret_cast<const float2*>(b2 + col);
                float v0 = fmaxf(acc[mt][nt][2 * pr + 0] + bb.x, 0.0f) * mv;
                float v1 = fmaxf(acc[mt][nt][2 * pr + 1] + bb.y, 0.0f) * mv;
                int tt = col >> 6;
                int ch = (col & 63) >> 3;
                *reinterpret_cast<uint32_t*>(smem + tt * 12288 + rl * 128 +
                    ((ch ^ (rl & 7)) << 4) + (col & 7) * 2) = packh2(v0, v1);
            }
        }
    }
#pragma unroll
    for (int i = 0; i < 2; i++)
#pragma unroll
        for (int jj = 0; jj < 4; jj++)
#pragma unroll
            for (int r = 0; r < 4; r++) acc[i][jj][r] = 0.0f;

    __syncthreads();                          // h2 visible (adj ready since G3)

    // ---- GEMM3: out = Aadj (96x96, 208B rows) @ h2 (96x256, A region) ----
#pragma unroll
    for (int s3 = 0; s3 < 6; s3++) {          // K=96 -> 6 k16 steps
        uint32_t afr[2][4];
#pragma unroll
        for (int mt = 0; mt < 2; mt++) {
            int m  = warpM + mt * 16 + (lane & 15);
            int ch = 2 * s3 + (lane >> 4);    // 0..11
            ldsm4(afr[mt], adjB + m * 208 + ch * 16);
        }
        uint32_t bfr[2][4];
#pragma unroll
        for (int np = 0; np < 2; np++) {
            int kl = s3 * 16 + (lane & 7) + 8 * ((lane >> 3) & 1);  // h2 row
            int gc = (warpN >> 3) + 2 * np + (lane >> 4);           // n chunk
            int tt = gc >> 3;
            int ch = gc & 7;
            ldsm4t(bfr[np], sBase + tt * 12288 + kl * 128 + ((ch ^ (kl & 7)) << 4));
        }
#pragma unroll
        for (int mt = 0; mt < 2; mt++)
#pragma unroll
            for (int np = 0; np < 2; np++) {
                mma16(acc[mt][2 * np + 0], afr[mt], bfr[np] + 0);
                mma16(acc[mt][2 * np + 1], afr[mt], bfr[np] + 2);
            }
    }

    // ---- epilogue3: out rows (b, i, j, :) fp32 ----
#pragma unroll
    for (int mt = 0; mt < 2; mt++) {
#pragma unroll
        for (int pr = 0; pr < 2; pr++) {
            int i = warpM + mt * 16 + grp + 8 * pr;    // 0..95
            size_t gr = ((size_t)(b * NN + i)) * NN + j;
#pragma unroll
            for (int nt = 0; nt < 4; nt++) {
                int col = warpN + nt * 8 + 2 * c4;
                *reinterpret_cast<float2*>(Out + gr * DD + col) =
                    make_float2(acc[mt][nt][2 * pr + 0], acc[mt][nt][2 * pr + 1]);
            }
        }
    }
}

// ---------------------------------------------------------------------------
// kernel_launch: inputs X, mask, A, W1, b1, W2, b2
// ---------------------------------------------------------------------------
extern "C" void kernel_launch(void* const* d_in, const int* in_sizes, int n_in,
                              void* d_out, int out_size)
{
    const float* X    = (const float*)d_in[0];
    const int*   mask = (const int*)d_in[1];
    const float* Aadj = (const float*)d_in[2];
    const float* W1   = (const float*)d_in[3];
    const float* b1   = (const float*)d_in[4];
    const float* W2   = (const float*)d_in[5];
    const float* b2   = (const float*)d_in[6];
    float*       out  = (float*)d_out;

    __half *w1h, *w2h, *ah;
    cudaGetSymbolAddress((void**)&w1h, g_W1h);
    cudaGetSymbolAddress((void**)&w2h, g_W2h);
    cudaGetSymbolAddress((void**)&ah,  g_Ah);

    const int FUSED_SMEM = 49152 + 20480 + 4 * 32768;    // 200704 = 196KB
    cudaFuncSetAttribute(mega24, cudaFuncAttributeMaxDynamicSharedMemorySize, FUSED_SMEM);

    // prepasses: transpose+cvt W1/W2 to fp16 [n][k]; cvt Aadj to fp16
    {
        dim3 tg(DD / 32, DD / 32);
        dim3 tb(32, 8);
        transpose_cvt_kernel<<<tg, tb>>>(W1, w1h);
        transpose_cvt_kernel<<<tg, tb>>>(W2, w2h);
        int a4 = (BB * NN * NN) / 4;
        cvt_half_kernel<<<(a4 + 255) / 256, 256>>>((const float4*)Aadj, (uint2*)ah, a4);
    }

    // mega-fused (24 warps, 4-stage B): MLP + mask + msgpass, h1/h2 in smem
    {
        dim3 grid(NN, BB);   // (96, 16) = 1536 CTAs
        mega24<<<grid, 768, FUSED_SMEM>>>(X, w1h, w2h, b1, b2, mask, ah, out);
    }
}

// round 17
// speedup vs baseline: 1.0807x; 1.0807x over previous
#include <cuda_runtime.h>
#include <cuda_fp16.h>
#include <cstdint>
#include <cstddef>

#define BB 16
#define NN 96
#define DD 256
#define MROWS (BB * NN * NN)          // 147456

// Scratch (allocation-free device globals)
__device__ __half g_W1h[DD * DD];    // transposed [n][k] fp16
__device__ __half g_W2h[DD * DD];    // transposed [n][k] fp16
__device__ __half g_Ah[BB * NN * NN];

// ---------------------------------------------------------------------------
// helpers
// ---------------------------------------------------------------------------
__device__ __forceinline__ uint32_t packh2(float a, float b) {
    __half2 h = __floats2half2_rn(a, b);
    return *reinterpret_cast<uint32_t*>(&h);
}

__device__ __forceinline__ void mma16(float* c, const uint32_t* a, const uint32_t* b) {
    asm volatile("mma.sync.aligned.m16n8k16.row.col.f32.f16.f16.f32 "
        "{%0,%1,%2,%3}, {%4,%5,%6,%7}, {%8,%9}, {%0,%1,%2,%3};"
        : "+f"(c[0]), "+f"(c[1]), "+f"(c[2]), "+f"(c[3])
        : "r"(a[0]), "r"(a[1]), "r"(a[2]), "r"(a[3]), "r"(b[0]), "r"(b[1]));
}

__device__ __forceinline__ void ldsm4(uint32_t* r, uint32_t addr) {
    asm volatile("ldmatrix.sync.aligned.m8n8.x4.shared.b16 {%0,%1,%2,%3}, [%4];"
        : "=r"(r[0]), "=r"(r[1]), "=r"(r[2]), "=r"(r[3]) : "r"(addr));
}

__device__ __forceinline__ void ldsm4t(uint32_t* r, uint32_t addr) {
    asm volatile("ldmatrix.sync.aligned.m8n8.x4.trans.shared.b16 {%0,%1,%2,%3}, [%4];"
        : "=r"(r[0]), "=r"(r[1]), "=r"(r[2]), "=r"(r[3]) : "r"(addr));
}

__device__ __forceinline__ void cpa16(uint32_t dst, const void* src) {
    asm volatile("cp.async.cg.shared.global [%0], [%1], 16;\n" :: "r"(dst), "l"(src));
}
__device__ __forceinline__ void cpa_commit() {
    asm volatile("cp.async.commit_group;\n");
}
template <int N>
__device__ __forceinline__ void cpa_wait() {
    asm volatile("cp.async.wait_group %0;\n" :: "n"(N));
}

// ---------------------------------------------------------------------------
// prepasses
// ---------------------------------------------------------------------------
__global__ void transpose_cvt_kernel(const float* __restrict__ src,
                                     __half* __restrict__ dst) {
    __shared__ float t[32][33];
    int bx = blockIdx.x * 32;
    int by = blockIdx.y * 32;
    int x = threadIdx.x, y0 = threadIdx.y;
#pragma unroll
    for (int r = 0; r < 32; r += 8)
        t[y0 + r][x] = src[(size_t)(by + y0 + r) * DD + bx + x];
    __syncthreads();
#pragma unroll
    for (int r = 0; r < 32; r += 8)
        dst[(size_t)(bx + y0 + r) * DD + by + x] = __float2half_rn(t[x][y0 + r]);
}

__global__ void cvt_half_kernel(const float4* __restrict__ src,
                                uint2* __restrict__ dst, int n4) {
    int i = blockIdx.x * blockDim.x + threadIdx.x;
    if (i < n4) {
        float4 v = src[i];
        uint2 o;
        o.x = packh2(v.x, v.y);
        o.y = packh2(v.z, v.w);
        dst[i] = o;
    }
}

// ---------------------------------------------------------------------------
// MEGA-FUSED, 24-warp, merged-barrier schedule. Per CTA (j, b): rows (b, i, j).
//   GEMM1: h1 = relu(X@W1+b1)        (M=96, N=256, K=256)
//   GEMM2: h2 = mask*relu(h1@W2+b2)  (h1 in smem, in place)
//   GEMM3: out[b,i,j,:] = sum_k Aadj[b,i,k]*h2[k,:]   (h2 in smem, K=96)
// 768 threads (24 warps, 6/SMSP), warp grid 3M x 8N, warp tile 32x32.
// smem: A 4x12KB (X->h1->h2 in place) + adj 20KB + B 2x32KB = 132KB.
// One wait+sync per tile: the pre-tile-(t+1) barrier proves all warps
// finished reading the stage being refilled -> refill issued right after it.
// ---------------------------------------------------------------------------
__global__ __launch_bounds__(768)
void mega24(const float* __restrict__ X, const __half* __restrict__ W1t,
            const __half* __restrict__ W2t, const float* __restrict__ b1,
            const float* __restrict__ b2, const int* __restrict__ mask,
            const __half* __restrict__ Aall, float* __restrict__ Out)
{
    extern __shared__ __align__(16) char smem[];
    const uint32_t sBase = (uint32_t)__cvta_generic_to_shared(smem);
    const uint32_t adjB  = sBase + 49152;     // 96 x 208B (pad to 20480)
    const uint32_t bBase = sBase + 69632;     // B: 2 stages x 32KB

    const int tid  = threadIdx.x;
    const int lane = tid & 31;
    const int warp = tid >> 5;                // 0..23
    const int grp  = lane >> 2;
    const int c4   = lane & 3;
    const int warpM = (warp >> 3) * 32;       // 0/32/64
    const int warpN = (warp & 7) * 32;        // 0..224
    const int j = blockIdx.x;                 // 0..95
    const int b = blockIdx.y;                 // 0..15

    float acc[2][4][4];
#pragma unroll
    for (int i = 0; i < 2; i++)
#pragma unroll
        for (int jj = 0; jj < 4; jj++)
#pragma unroll
            for (int r = 0; r < 4; r++) acc[i][jj][r] = 0.0f;

    // X tile loader: rows (b, row, j), 96 rows x 8 chunks = 768 -> 1/thread
    auto ldX = [&](int t) {
        int row = tid >> 3, ch = tid & 7;
        size_t gr = ((size_t)(b * NN + row)) * NN + j;
        const float* p = X + gr * DD + t * 64 + ch * 8;
        float4 u = *reinterpret_cast<const float4*>(p);
        float4 v = *reinterpret_cast<const float4*>(p + 4);
        uint4 val;
        val.x = packh2(u.x, u.y);
        val.y = packh2(u.z, u.w);
        val.z = packh2(v.x, v.y);
        val.w = packh2(v.z, v.w);
        *reinterpret_cast<uint4*>(smem + t * 12288 + row * 128 +
                                  ((ch ^ (row & 7)) << 4)) = val;
    };
    // B loader: 256 rows x 8 chunks = 2048 -> 3 reps, last partial
    auto cpaB = [&](const __half* Wt, int t, int stage) {
#pragma unroll
        for (int rep = 0; rep < 3; rep++) {
            int g = tid + rep * 768;
            if (g < 2048) {
                int row = g >> 3, ch = g & 7;
                cpa16(bBase + stage * 32768 + row * 128 + ((ch ^ (row & 7)) << 4),
                      Wt + (size_t)row * DD + t * 64 + ch * 8);
            }
        }
    };
    auto cpaAdj = [&]() {
        const __half* Aab = Aall + (size_t)b * NN * NN;
#pragma unroll
        for (int rep = 0; rep < 2; rep++) {
            int idx = tid + rep * 768;
            if (idx < 96 * 12) {
                int row = idx / 12, ch = idx % 12;
                cpa16(adjB + row * 208 + ch * 16, Aab + row * 96 + ch * 8);
            }
        }
    };

    auto computeTile = [&](uint32_t aSt, uint32_t bSt) {
#pragma unroll
        for (int ks = 0; ks < 4; ks++) {
            uint32_t afr[2][4];
#pragma unroll
            for (int mt = 0; mt < 2; mt++) {
                int m  = warpM + mt * 16 + (lane & 15);
                int ch = 2 * ks + (lane >> 4);
                ldsm4(afr[mt], aSt + m * 128 + ((ch ^ (m & 7)) << 4));
            }
            uint32_t bfr[2][4];
#pragma unroll
            for (int np = 0; np < 2; np++) {
                int n  = warpN + np * 16 + 8 * (lane >> 4) + (lane & 7);
                int ch = 2 * ks + ((lane >> 3) & 1);
                ldsm4(bfr[np], bSt + n * 128 + ((ch ^ (n & 7)) << 4));
            }
#pragma unroll
            for (int mt = 0; mt < 2; mt++)
#pragma unroll
                for (int np = 0; np < 2; np++) {
                    mma16(acc[mt][2 * np + 0], afr[mt], bfr[np] + 0);
                    mma16(acc[mt][2 * np + 1], afr[mt], bfr[np] + 2);
                }
        }
    };

    // ---- prologue: adj + W1 t0 as G0, W1 t1 as G1; X staged (as R15) ----
    cpaAdj(); cpaB(W1t, 0, 0); cpa_commit();  // G0 (adj rides along)
    cpaB(W1t, 1, 1); cpa_commit();            // G1
    ldX(0); ldX(1); ldX(2); ldX(3);

    // ---- GEMM1: h1 = X @ W1; one wait+sync per tile ----
    cpa_wait<1>(); __syncthreads();           // G0 done (adj + W1 t0)
    computeTile(sBase + 0 * 12288, bBase + 0 * 32768);

    cpa_wait<0>(); __syncthreads();           // G1 done; all warps past t0
    cpaB(W1t, 2, 0); cpa_commit();            // G2 -> s0 (readers proven done)
    computeTile(sBase + 1 * 12288, bBase + 1 * 32768);

    cpa_wait<0>(); __syncthreads();           // G2 done; all past t1
    cpaB(W1t, 3, 1); cpa_commit();            // G3 -> s1
    computeTile(sBase + 2 * 12288, bBase + 0 * 32768);

    cpa_wait<0>(); __syncthreads();           // G3 done; all past t2
    cpaB(W2t, 0, 0); cpa_commit();            // G4 -> s0
    computeTile(sBase + 3 * 12288, bBase + 1 * 32768);

    __syncthreads();                          // all X + s1 reads done
    cpaB(W2t, 1, 1); cpa_commit();            // G5 -> s1

    // ---- epilogue1: h1 = relu(acc + b1) -> A region (fp16), zero acc ----
#pragma unroll
    for (int mt = 0; mt < 2; mt++) {
#pragma unroll
        for (int pr = 0; pr < 2; pr++) {
            int rl = warpM + mt * 16 + grp + 8 * pr;   // 0..95
#pragma unroll
            for (int nt = 0; nt < 4; nt++) {
                int col = warpN + nt * 8 + 2 * c4;
                float2 bb = *reinterpret_cast<const float2*>(b1 + col);
                float v0 = fmaxf(acc[mt][nt][2 * pr + 0] + bb.x, 0.0f);
                float v1 = fmaxf(acc[mt][nt][2 * pr + 1] + bb.y, 0.0f);
                int tt = col >> 6;
                int ch = (col & 63) >> 3;
                *reinterpret_cast<uint32_t*>(smem + tt * 12288 + rl * 128 +
                    ((ch ^ (rl & 7)) << 4) + (col & 7) * 2) = packh2(v0, v1);
            }
        }
    }
#pragma unroll
    for (int i = 0; i < 2; i++)
#pragma unroll
        for (int jj = 0; jj < 4; jj++)
#pragma unroll
            for (int r = 0; r < 4; r++) acc[i][jj][r] = 0.0f;

    // ---- GEMM2: h2 = h1 @ W2; one wait+sync per tile ----
    cpa_wait<1>(); __syncthreads();           // G4 done + h1 visible
    computeTile(sBase + 0 * 12288, bBase + 0 * 32768);

    cpa_wait<0>(); __syncthreads();           // G5 done; all past t0
    cpaB(W2t, 2, 0); cpa_commit();            // G6 -> s0
    computeTile(sBase + 1 * 12288, bBase + 1 * 32768);

    cpa_wait<0>(); __syncthreads();           // G6 done; all past t1
    cpaB(W2t, 3, 1); cpa_commit();            // G7 -> s1
    computeTile(sBase + 2 * 12288, bBase + 0 * 32768);

    cpa_wait<0>(); __syncthreads();           // G7 done; all past t2
    computeTile(sBase + 3 * 12288, bBase + 1 * 32768);

    __syncthreads();                          // all h1 reads done

    // ---- epilogue2: h2 = mask * relu(acc + b2) -> A region (fp16) ----
#pragma unroll
    for (int mt = 0; mt < 2; mt++) {
#pragma unroll
        for (int pr = 0; pr < 2; pr++) {
            int rl = warpM + mt * 16 + grp + 8 * pr;   // 0..95 (= i)
            float mv = (mask[((size_t)(b * NN + rl)) * NN + j] != 0) ? 1.0f : 0.0f;
#pragma unroll
            for (int nt = 0; nt < 4; nt++) {
                int col = warpN + nt * 8 + 2 * c4;
                float2 bb = *reinterpret_cast<const float2*>(b2 + col);
                float v0 = fmaxf(acc[mt][nt][2 * pr + 0] + bb.x, 0.0f) * mv;
                float v1 = fmaxf(acc[mt][nt][2 * pr + 1] + bb.y, 0.0f) * mv;
                int tt = col >> 6;
                int ch = (col & 63) >> 3;
                *reinterpret_cast<uint32_t*>(smem + tt * 12288 + rl * 128 +
                    ((ch ^ (rl & 7)) << 4) + (col & 7) * 2) = packh2(v0, v1);
            }
        }
    }
#pragma unroll
    for (int i = 0; i < 2; i++)
#pragma unroll
        for (int jj = 0; jj < 4; jj++)
#pragma unroll
            for (int r = 0; r < 4; r++) acc[i][jj][r] = 0.0f;

    __syncthreads();                          // h2 visible (adj ready since G0)

    // ---- GEMM3: out = Aadj (96x96, 208B rows) @ h2 (96x256, A region) ----
#pragma unroll
    for (int s3 = 0; s3 < 6; s3++) {          // K=96 -> 6 k16 steps
        uint32_t afr[2][4];
#pragma unroll
        for (int mt = 0; mt < 2; mt++) {
            int m  = warpM + mt * 16 + (lane & 15);
            int ch = 2 * s3 + (lane >> 4);    // 0..11
            ldsm4(afr[mt], adjB + m * 208 + ch * 16);
        }
        uint32_t bfr[2][4];
#pragma unroll
        for (int np = 0; np < 2; np++) {
            int kl = s3 * 16 + (lane & 7) + 8 * ((lane >> 3) & 1);  // h2 row
            int gc = (warpN >> 3) + 2 * np + (lane >> 4);           // n chunk
            int tt = gc >> 3;
            int ch = gc & 7;
            ldsm4t(bfr[np], sBase + tt * 12288 + kl * 128 + ((ch ^ (kl & 7)) << 4));
        }
#pragma unroll
        for (int mt = 0; mt < 2; mt++)
#pragma unroll
            for (int np = 0; np < 2; np++) {
                mma16(acc[mt][2 * np + 0], afr[mt], bfr[np] + 0);
                mma16(acc[mt][2 * np + 1], afr[mt], bfr[np] + 2);
            }
    }

    // ---- epilogue3: out rows (b, i, j, :) fp32 ----
#pragma unroll
    for (int mt = 0; mt < 2; mt++) {
#pragma unroll
        for (int pr = 0; pr < 2; pr++) {
            int i = warpM + mt * 16 + grp + 8 * pr;    // 0..95
            size_t gr = ((size_t)(b * NN + i)) * NN + j;
#pragma unroll
            for (int nt = 0; nt < 4; nt++) {
                int col = warpN + nt * 8 + 2 * c4;
                *reinterpret_cast<float2*>(Out + gr * DD + col) =
                    make_float2(acc[mt][nt][2 * pr + 0], acc[mt][nt][2 * pr + 1]);
            }
        }
    }
}

// ---------------------------------------------------------------------------
// kernel_launch: inputs X, mask, A, W1, b1, W2, b2
// ---------------------------------------------------------------------------
extern "C" void kernel_launch(void* const* d_in, const int* in_sizes, int n_in,
                              void* d_out, int out_size)
{
    const float* X    = (const float*)d_in[0];
    const int*   mask = (const int*)d_in[1];
    const float* Aadj = (const float*)d_in[2];
    const float* W1   = (const float*)d_in[3];
    const float* b1   = (const float*)d_in[4];
    const float* W2   = (const float*)d_in[5];
    const float* b2   = (const float*)d_in[6];
    float*       out  = (float*)d_out;

    __half *w1h, *w2h, *ah;
    cudaGetSymbolAddress((void**)&w1h, g_W1h);
    cudaGetSymbolAddress((void**)&w2h, g_W2h);
    cudaGetSymbolAddress((void**)&ah,  g_Ah);

    const int FUSED_SMEM = 49152 + 20480 + 2 * 32768;    // 135168 = 132KB
    cudaFuncSetAttribute(mega24, cudaFuncAttributeMaxDynamicSharedMemorySize, FUSED_SMEM);

    // prepasses: transpose+cvt W1/W2 to fp16 [n][k]; cvt Aadj to fp16
    {
        dim3 tg(DD / 32, DD / 32);
        dim3 tb(32, 8);
        transpose_cvt_kernel<<<tg, tb>>>(W1, w1h);
        transpose_cvt_kernel<<<tg, tb>>>(W2, w2h);
        int a4 = (BB * NN * NN) / 4;
        cvt_half_kernel<<<(a4 + 255) / 256, 256>>>((const float4*)Aadj, (uint2*)ah, a4);
    }

    // mega-fused (24 warps, merged barriers): MLP + mask + msgpass in one kernel
    {
        dim3 grid(NN, BB);   // (96, 16) = 1536 CTAs
        mega24<<<grid, 768, FUSED_SMEM>>>(X, w1h, w2h, b1, b2, mask, ah, out);
    }
}